// round 16
// baseline (speedup 1.0000x reference)
#include <cuda_runtime.h>
#include <cuda_bf16.h>

#define BB 16
#define TT 512
#define CC 1024
#define DD 4096
#define KK 128
#define WW 8
#define NW 127
#define NN (BB*TT)

#define PFIX_DELTA 5e-3f
#define MARGIN_W 5e-2f
#define MARGIN_V 3e-2f
#define BCAP 256
#define ECAP 96

// ---------------- scratch (device globals; no allocation allowed) ----------------
__device__ float g_post[(size_t)NN*DD];            // PRE-activations (no relu); near-zero entries exact
__device__ float g_off[DD];
__device__ unsigned char g_maskw[(size_t)BB*NW*DD];
__device__ unsigned short g_idx[(size_t)NN*KK];
__device__ float g_val[(size_t)NN*KK];
__device__ float g_pooled[BB*DD];
__device__ float g_losspart[NN];
__device__ float g_Ah[(size_t)NN*CC];              // tf32(x)
__device__ float g_Bh[(size_t)DD*CC];              // tf32(W_enc)
__device__ unsigned short g_Wbf[(size_t)DD*CC];    // bf16(W_enc) for recon

__device__ __forceinline__ float to_tf32(float x) {
    float y;
    asm("cvt.rna.tf32.f32 %0, %1;" : "=f"(y) : "f"(x));
    return y;
}
__device__ __forceinline__ void cp16(unsigned dst, const float* src) {
    asm volatile("cp.async.cg.shared.global [%0], [%1], 16;" :: "r"(dst), "l"(src) : "memory");
}

// warp-collective exact fp32 dot (global x, global W): lane-strided chains + shfl tree.
__device__ __forceinline__ float exact_pre_warp(const float* __restrict__ xr,
                                                const float* __restrict__ wr, int lane) {
    float acc = 0.f;
    #pragma unroll 8
    for (int k = lane; k < CC; k += 32) acc = fmaf(xr[k], wr[k], acc);
    #pragma unroll
    for (int o = 16; o; o >>= 1) acc += __shfl_xor_sync(0xffffffffu, acc, o);
    return acc;
}

// ---------------- pre-convert: tf32(x) ----------------
__global__ __launch_bounds__(256) void k_split_x(const float* __restrict__ src) {
    int i = blockIdx.x * blockDim.x + threadIdx.x;
    float4 v = ((const float4*)src)[i];
    float4 h;
    h.x = to_tf32(v.x); h.y = to_tf32(v.y); h.z = to_tf32(v.z); h.w = to_tf32(v.w);
    ((float4*)g_Ah)[i] = h;
}
// ---------------- W: one read -> tf32 copy + bf16 copy ----------------
__global__ __launch_bounds__(256) void k_split_w(const float* __restrict__ src) {
    int i = blockIdx.x * blockDim.x + threadIdx.x;
    float4 v = ((const float4*)src)[i];
    float4 h;
    h.x = to_tf32(v.x); h.y = to_tf32(v.y); h.z = to_tf32(v.z); h.w = to_tf32(v.w);
    ((float4*)g_Bh)[i] = h;
    unsigned b0 = __bfloat16_as_ushort(__float2bfloat16(v.x));
    unsigned b1 = __bfloat16_as_ushort(__float2bfloat16(v.y));
    unsigned b2 = __bfloat16_as_ushort(__float2bfloat16(v.z));
    unsigned b3 = __bfloat16_as_ushort(__float2bfloat16(v.w));
    uint2 o;
    o.x = b0 | (b1 << 16);
    o.y = b2 | (b3 << 16);
    ((uint2*)g_Wbf)[i] = o;
}

// ---------------- offset precompute ----------------
__global__ void k_off(const float* __restrict__ b_enc, const float* __restrict__ b_dec,
                      const float* __restrict__ W_enc) {
    int warp = (blockIdx.x * blockDim.x + threadIdx.x) >> 5;
    int lane = threadIdx.x & 31;
    if (warp >= DD) return;
    const float* wr = W_enc + (size_t)warp * CC;
    float s = 0.f;
    for (int c = lane; c < CC; c += 32) s += b_dec[c] * wr[c];
    #pragma unroll
    for (int o = 16; o; o >>= 1) s += __shfl_down_sync(0xffffffffu, s, o);
    if (lane == 0) g_off[warp] = b_enc[warp] - s;
}

__global__ void k_zero_pooled() {
    int i = blockIdx.x * blockDim.x + threadIdx.x;
    if (i < BB*DD) g_pooled[i] = 0.f;
}

// ---------------- encoder GEMM: SINGLE-term tf32, stores PRE; 3 blocks/SM ----------
#define T_STR 20
#define TILE_F (128*T_STR)
#define STG_F (2*TILE_F)
__global__ __launch_bounds__(256, 3) void k_gemm_enc_tc() {
    extern __shared__ float sm[];
    int tid = threadIdx.x;
    int wid = tid >> 5, lane = tid & 31;
    int g = lane >> 2, tg = lane & 3;
    int wm = wid >> 2, wn = wid & 3;
    const size_t arow = (size_t)blockIdx.x * 128;
    const size_t brow = (size_t)blockIdx.y * 128;
    unsigned smb = (unsigned)__cvta_generic_to_shared(sm);

    float c[4][4][4];
    #pragma unroll
    for (int mi = 0; mi < 4; mi++)
        #pragma unroll
        for (int ni = 0; ni < 4; ni++)
            #pragma unroll
            for (int r = 0; r < 4; r++) c[mi][ni][r] = 0.f;

    auto FILL = [&](int st, int k0) {
        #pragma unroll
        for (int p = 0; p < 2; p++) {
            int ch = tid + p * 256;
            int row = ch >> 2, c4 = (ch & 3) << 2;
            unsigned d = smb + (unsigned)((st*STG_F + row*T_STR + c4) * 4);
            cp16(d,            g_Ah + (arow + row) * CC + k0 + c4);
            cp16(d + TILE_F*4, g_Bh + (brow + row) * CC + k0 + c4);
        }
    };

    FILL(0, 0);
    asm volatile("cp.async.commit_group;" ::: "memory");

    for (int j = 0; j < 64; j++) {
        int s = j & 1;
        if (j < 63) {
            FILL(s ^ 1, (j + 1) * 16);
            asm volatile("cp.async.commit_group;" ::: "memory");
            asm volatile("cp.async.wait_group 1;" ::: "memory");
        } else {
            asm volatile("cp.async.wait_group 0;" ::: "memory");
        }
        __syncthreads();
        const float* Ah = sm + s*STG_F;
        const float* Bh = Ah + TILE_F;
        #pragma unroll
        for (int kk = 0; kk < 2; kk++) {
            int kb = kk * 8;
            unsigned ah[4][4], bh[4][2];
            #pragma unroll
            for (int mi = 0; mi < 4; mi++) {
                int r = wm*64 + mi*16 + g;
                const float* p0 = Ah + r*T_STR + kb + tg;
                ah[mi][0]=__float_as_uint(p0[0]);      ah[mi][1]=__float_as_uint(p0[8*T_STR]);
                ah[mi][2]=__float_as_uint(p0[4]);      ah[mi][3]=__float_as_uint(p0[8*T_STR+4]);
            }
            #pragma unroll
            for (int ni = 0; ni < 4; ni++) {
                int n = wn*32 + ni*8 + g;
                const float* q0 = Bh + n*T_STR + kb + tg;
                bh[ni][0]=__float_as_uint(q0[0]);      bh[ni][1]=__float_as_uint(q0[4]);
            }
            #pragma unroll
            for (int mi = 0; mi < 4; mi++)
                #pragma unroll
                for (int ni = 0; ni < 4; ni++)
                    asm volatile(
                        "mma.sync.aligned.m16n8k8.row.col.f32.tf32.tf32.f32 "
                        "{%0,%1,%2,%3}, {%4,%5,%6,%7}, {%8,%9}, {%0,%1,%2,%3};"
                        : "+f"(c[mi][ni][0]), "+f"(c[mi][ni][1]),
                          "+f"(c[mi][ni][2]), "+f"(c[mi][ni][3])
                        : "r"(ah[mi][0]), "r"(ah[mi][1]), "r"(ah[mi][2]), "r"(ah[mi][3]),
                          "r"(bh[ni][0]), "r"(bh[ni][1]));
        }
        __syncthreads();
    }

    int n0 = (int)arow + wm*64;
    int d0 = (int)brow + wn*32;
    #pragma unroll
    for (int ni = 0; ni < 4; ni++) {
        int col = d0 + ni*8 + 2*tg;
        float o0 = g_off[col], o1 = g_off[col+1];
        #pragma unroll
        for (int mi = 0; mi < 4; mi++) {
            int r0 = n0 + mi*16 + g;
            float2 v0, v1;
            v0.x = c[mi][ni][0] + o0;  v0.y = c[mi][ni][1] + o1;
            v1.x = c[mi][ni][2] + o0;  v1.y = c[mi][ni][3] + o1;
            *(float2*)(g_post + (size_t)r0*DD + col)     = v0;
            *(float2*)(g_post + (size_t)(r0+8)*DD + col) = v1;
        }
    }
}

// ---------------- post-fix: exact recompute of all |pre| <= PFIX_DELTA entries ----------------
__global__ __launch_bounds__(256) void k_pfix(const float* __restrict__ X,
                                              const float* __restrict__ W) {
    int wid = threadIdx.x >> 5, lane = threadIdx.x & 31;
    size_t base = ((size_t)blockIdx.x * 8 + wid) * 256;
    #pragma unroll
    for (int i = 0; i < 8; i++) {
        float v = g_post[base + i*32 + lane];
        unsigned fl = __ballot_sync(0xffffffffu, fabsf(v) <= PFIX_DELTA);
        while (fl) {
            int src = __ffs(fl) - 1; fl &= fl - 1;
            size_t e2 = base + i*32 + src;
            int n = (int)(e2 >> 12), d = (int)(e2 & 4095);
            float p = exact_pre_warp(X + (size_t)n*CC, W + (size_t)d*CC, lane);
            if (lane == src) g_post[e2] = p;
        }
    }
}

// ---------------- exact top-128 of 4096 distinct 44-bit keys: radix + early-exit rank -------
// After each 8-bit pass, if the surviving set (hist[chosen]) fits in ECAP, collect it and
// rank exactly with full 44-bit compares. Zero-value clusters fall through to full passes.
__device__ __forceinline__ unsigned long long radix_select_128(
        const unsigned long long* skey, int tid) {
    __shared__ int hist[256];
    __shared__ unsigned long long sh_prefix;
    __shared__ unsigned long long sh_thr;
    __shared__ unsigned long long elist[ECAP];
    __shared__ int sh_krem, sh_cnt, sh_ecnt;
    if (tid == 0) { sh_prefix = 0ULL; sh_krem = KK; sh_cnt = 1 << 30; }
    __syncthreads();
    int done_shift = -1;
    for (int pass = 0; pass < 6; pass++) {
        int shift = 40 - 8 * pass;
        if (tid < 256) hist[tid] = 0;
        __syncthreads();
        unsigned long long pfx = sh_prefix;
        int krem = sh_krem;
        #pragma unroll
        for (int i = 0; i < 8; i++) {
            unsigned long long key = skey[tid + i * 512];
            bool ok = (pass == 0) || ((key >> (shift + 8)) == (pfx >> (shift + 8)));
            unsigned am = __ballot_sync(0xffffffffu, ok);
            if (ok) {
                int bucket = (int)((key >> shift) & 255ULL);
                unsigned m = __match_any_sync(am, bucket);
                if ((tid & 31) == (__ffs(m) - 1))
                    atomicAdd(&hist[bucket], __popc(m));
            }
        }
        __syncthreads();
        if (tid < 32) {
            int base = tid * 8, suf[8], s = 0;
            #pragma unroll
            for (int j = 7; j >= 0; j--) { s += hist[base + j]; suf[j] = s; }
            int t = s;
            #pragma unroll
            for (int off = 1; off < 32; off <<= 1) {
                int u = __shfl_down_sync(0xffffffffu, t, off);
                if (tid + off < 32) t += u;
            }
            int above = t - s;
            __syncwarp();
            #pragma unroll
            for (int j = 0; j < 8; j++) {
                int Sj = suf[j] + above;
                int Sn = (j < 7 ? suf[j+1] : 0) + above;
                if (Sj >= krem && Sn < krem) {
                    sh_prefix = pfx | ((unsigned long long)(base + j) << shift);
                    sh_krem = krem - Sn;
                    sh_cnt = hist[base + j];
                }
            }
        }
        __syncthreads();
        if (sh_cnt <= ECAP) { done_shift = shift; break; }
    }
    if (done_shift < 0) return sh_prefix;   // all 6 passes done: prefix IS the key
    // collect survivors and rank exactly
    if (tid == 0) sh_ecnt = 0;
    __syncthreads();
    unsigned long long pfx = sh_prefix;
    #pragma unroll
    for (int i = 0; i < 8; i++) {
        unsigned long long key = skey[tid + i * 512];
        if ((key >> done_shift) == (pfx >> done_shift)) {
            int s = atomicAdd(&sh_ecnt, 1);
            if (s < ECAP) elist[s] = key;
        }
    }
    __syncthreads();
    int cnt = sh_ecnt < ECAP ? sh_ecnt : ECAP;
    int krem = sh_krem;
    if (tid < cnt) {
        int rank = 0;
        for (int j = 0; j < cnt; j++) rank += (elist[j] > elist[tid]);
        if (rank == krem - 1) sh_thr = elist[tid];
    }
    __syncthreads();
    return sh_thr;
}

// ---------------- window sums + top-k mask; smem-staged x, warp-per-candidate fixup ----------
#define WT_SMEM (32768 + 32768 + BCAP*8*4 + BCAP*8 + BCAP*4)
__global__ __launch_bounds__(512) void k_wtopk(const float* __restrict__ X,
                                               const float* __restrict__ W) {
    extern __shared__ char smraw[];
    unsigned long long* skey = (unsigned long long*)smraw;
    float* sx = (float*)(smraw + 32768);
    float (*bd_post)[8] = (float(*)[8])(smraw + 65536);
    unsigned long long* bd_key = (unsigned long long*)(smraw + 65536 + BCAP*32);
    int* bd_d = (int*)(smraw + 65536 + BCAP*32 + BCAP*8);
    __shared__ int sh_bcnt, sh_bin;
    int tid = threadIdx.x;
    int wrp = tid >> 5, lane = tid & 31;
    int b = blockIdx.x / NW, w = blockIdx.x % NW;
    int t0 = w * 4;
    const float* base = g_post + ((size_t)(b*TT + t0)) * DD;
    if (tid == 0) { sh_bcnt = 0; sh_bin = 0; }
    for (int i = tid; i < 8 * CC / 4; i += 512) {
        int t = i / (CC/4), c4 = (i % (CC/4)) * 4;
        *(float4*)&sx[t*CC + c4] = *(const float4*)(X + (size_t)(b*TT + t0 + t)*CC + c4);
    }
    #pragma unroll
    for (int i = 0; i < 8; i++) {
        int d = tid + i * 512;
        float s = 0.f;
        #pragma unroll
        for (int t = 0; t < 8; t++) s += fmaxf(base[(size_t)t*DD + d], 0.f);
        unsigned vb = (s > 0.f) ? __float_as_uint(s) : 0u;
        skey[d] = ((unsigned long long)vb << 12) | (unsigned long long)(0xFFFu - (unsigned)d);
    }
    __syncthreads();
    unsigned long long thr = radix_select_128(skey, tid);
    float thr_val = __uint_as_float((unsigned)(thr >> 12));
    #pragma unroll
    for (int i = 0; i < 8; i++) {
        int d = tid + i * 512;
        unsigned long long key = skey[d];
        float s = __uint_as_float((unsigned)(key >> 12));
        if (fabsf(s - thr_val) <= MARGIN_W) {
            int idx = atomicAdd(&sh_bcnt, 1);
            if (idx < BCAP) {
                bd_d[idx] = d;
                if (key >= thr) atomicAdd(&sh_bin, 1);
            }
        }
    }
    __syncthreads();
    int bcnt = sh_bcnt;
    if (bcnt > BCAP) bcnt = 0;
    int n_need = sh_bin;
    for (int ci = wrp; ci < bcnt; ci += 16) {
        const float* wr = W + (size_t)bd_d[ci] * CC;
        #pragma unroll
        for (int t = 0; t < 8; t++) {
            float acc = 0.f;
            #pragma unroll 8
            for (int k = lane; k < CC; k += 32) acc = fmaf(sx[t*CC + k], wr[k], acc);
            #pragma unroll
            for (int o = 16; o; o >>= 1) acc += __shfl_xor_sync(0xffffffffu, acc, o);
            if (lane == 0) bd_post[ci][t] = fmaxf(acc, 0.f);
        }
    }
    __syncthreads();
    if (tid < bcnt) {
        float s = 0.f;
        #pragma unroll
        for (int t = 0; t < 8; t++) s += bd_post[tid][t];
        unsigned vb = (s > 0.f) ? __float_as_uint(s) : 0u;
        bd_key[tid] = ((unsigned long long)vb << 12) | (unsigned long long)(0xFFFu - (unsigned)bd_d[tid]);
    }
    __syncthreads();
    unsigned char* mw = g_maskw + ((size_t)(b*NW + w)) * DD;
    #pragma unroll
    for (int i = 0; i < 8; i++) {
        int d = tid + i * 512;
        unsigned long long key = skey[d];
        float s = __uint_as_float((unsigned)(key >> 12));
        bool bdy = (bcnt > 0) && (fabsf(s - thr_val) <= MARGIN_W);
        mw[d] = (key >= thr && !bdy) ? (unsigned char)1 : (unsigned char)0;
    }
    __syncthreads();
    if (tid < bcnt) {
        int rank = 0;
        for (int j = 0; j < bcnt; j++) rank += (bd_key[j] > bd_key[tid]);
        mw[bd_d[tid]] = (rank < n_need) ? (unsigned char)1 : (unsigned char)0;
    }
}

// ---------------- votes + combined top-k + sparse encode; smem x; raw-pre candidates ---------
__global__ __launch_bounds__(512) void k_ctopk(const float* __restrict__ X,
                                               const float* __restrict__ W) {
    __shared__ unsigned long long skey[DD];
    __shared__ unsigned char scnt[DD];
    __shared__ float sx[CC];
    __shared__ int bd_d[BCAP];
    __shared__ unsigned char bd_c[BCAP];
    __shared__ float bd_v[BCAP];          // RAW pre (can be negative)
    __shared__ unsigned long long bd_key[BCAP];
    __shared__ int sh_bcnt, sh_bin, s_cnt;
    int tid = threadIdx.x;
    int wrp = tid >> 5, lane = tid & 31;
    int n = blockIdx.x;
    int b = n >> 9, t = n & 511;
    int g = t >> 2;
    const float* pr = g_post + (size_t)n * DD;
    const unsigned char* mw0 = (g >= 1)   ? g_maskw + ((size_t)(b*NW + g-1))*DD : (const unsigned char*)0;
    const unsigned char* mw1 = (g <= 126) ? g_maskw + ((size_t)(b*NW + g  ))*DD : (const unsigned char*)0;
    if (tid == 0) { sh_bcnt = 0; sh_bin = 0; s_cnt = 0; }
    for (int i = tid; i < CC/4; i += 512)
        *(float4*)&sx[i*4] = *(const float4*)(X + (size_t)n*CC + i*4);
    #pragma unroll
    for (int i = 0; i < 8; i++) {
        int d = tid + i * 512;
        float v = fmaxf(pr[d], 0.f);
        int c = (mw0 ? (int)mw0[d] : 0) + (mw1 ? (int)mw1[d] : 0);
        scnt[d] = (unsigned char)c;
        float vote = v * (float)c;
        unsigned vb = (vote > 0.f) ? __float_as_uint(vote) : 0u;
        skey[d] = ((unsigned long long)vb << 12) | (unsigned long long)(0xFFFu - (unsigned)d);
    }
    __syncthreads();
    unsigned long long thr = radix_select_128(skey, tid);
    float thr_val = __uint_as_float((unsigned)(thr >> 12));
    #pragma unroll
    for (int i = 0; i < 8; i++) {
        int d = tid + i * 512;
        unsigned long long key = skey[d];
        float v = __uint_as_float((unsigned)(key >> 12));
        if (scnt[d] > 0 && fabsf(v - thr_val) <= MARGIN_V) {
            int idx = atomicAdd(&sh_bcnt, 1);
            if (idx < BCAP) {
                bd_d[idx] = d;
                bd_c[idx] = scnt[d];
                bd_v[idx] = pr[d];
                if (key >= thr) atomicAdd(&sh_bin, 1);
            }
        }
    }
    __syncthreads();
    int bcnt = sh_bcnt;
    if (bcnt > BCAP) bcnt = 0;
    int n_need = sh_bin;
    for (int ci = wrp; ci < bcnt; ci += 16) {
        float raw = bd_v[ci];
        float pe;
        if (fabsf(raw) <= PFIX_DELTA) {
            pe = fmaxf(raw, 0.f);
        } else {
            const float* wr = W + (size_t)bd_d[ci] * CC;
            float acc = 0.f;
            #pragma unroll 8
            for (int k = lane; k < CC; k += 32) acc = fmaf(sx[k], wr[k], acc);
            #pragma unroll
            for (int o = 16; o; o >>= 1) acc += __shfl_xor_sync(0xffffffffu, acc, o);
            pe = fmaxf(acc, 0.f);
        }
        if (lane == 0) {
            float ve = pe * (float)bd_c[ci];
            unsigned vb = (ve > 0.f) ? __float_as_uint(ve) : 0u;
            bd_key[ci] = ((unsigned long long)vb << 12) | (unsigned long long)(0xFFFu - (unsigned)bd_d[ci]);
        }
    }
    __syncthreads();
    #pragma unroll
    for (int i = 0; i < 8; i++) {
        int d = tid + i * 512;
        unsigned long long key = skey[d];
        float v = __uint_as_float((unsigned)(key >> 12));
        bool bdy = (bcnt > 0) && (scnt[d] > 0) && (fabsf(v - thr_val) <= MARGIN_V);
        if (key >= thr && !bdy) {
            int slot = atomicAdd(&s_cnt, 1);
            g_idx[(size_t)n*KK + slot] = (unsigned short)d;
            g_val[(size_t)n*KK + slot] = fmaxf(pr[d], 0.f);
        }
    }
    __syncthreads();
    if (tid < bcnt) {
        int rank = 0;
        for (int j = 0; j < bcnt; j++) rank += (bd_key[j] > bd_key[tid]);
        if (rank < n_need) {
            int slot = atomicAdd(&s_cnt, 1);
            g_idx[(size_t)n*KK + slot] = (unsigned short)bd_d[tid];
            g_val[(size_t)n*KK + slot] = fmaxf(pr[bd_d[tid]], 0.f);
        }
    }
}

// ---------------- sparse recon (bf16 W) + per-row squared error + pooled accumulation --------
__global__ __launch_bounds__(256) void k_recon(const float* __restrict__ X,
                                               const float* __restrict__ b_dec) {
    __shared__ unsigned short sidx[KK];
    __shared__ float sval[KK];
    __shared__ float sred[256];
    int tid = threadIdx.x;
    int n = blockIdx.x;
    if (tid < KK) {
        sidx[tid] = g_idx[(size_t)n*KK + tid];
        sval[tid] = g_val[(size_t)n*KK + tid];
    }
    __syncthreads();
    int c = tid * 4;
    float4 acc = make_float4(0.f, 0.f, 0.f, 0.f);
    #pragma unroll 4
    for (int j = 0; j < KK; j++) {
        float v = sval[j];
        uint2 p = *(const uint2*)(g_Wbf + (size_t)sidx[j]*CC + c);
        float w0 = __uint_as_float(p.x << 16);
        float w1 = __uint_as_float(p.x & 0xFFFF0000u);
        float w2 = __uint_as_float(p.y << 16);
        float w3 = __uint_as_float(p.y & 0xFFFF0000u);
        acc.x += v*w0; acc.y += v*w1; acc.z += v*w2; acc.w += v*w3;
    }
    float4 bd = *(const float4*)(b_dec + c);
    float4 xv = *(const float4*)(X + (size_t)n*CC + c);
    float dx = acc.x + bd.x - xv.x;
    float dy = acc.y + bd.y - xv.y;
    float dz = acc.z + bd.z - xv.z;
    float dw = acc.w + bd.w - xv.w;
    sred[tid] = dx*dx + dy*dy + dz*dz + dw*dw;
    __syncthreads();
    for (int s = 128; s > 0; s >>= 1) {
        if (tid < s) sred[tid] += sred[tid + s];
        __syncthreads();
    }
    if (tid == 0) g_losspart[n] = sred[0];
    if (tid < KK) {
        int b = n >> 9;
        atomicAdd(&g_pooled[b*DD + sidx[tid]], sval[tid] * (1.f/512.f));
    }
}

// ---------------- LayerNorm + MLP head + log_softmax ----------------
__global__ __launch_bounds__(256) void k_head(const float* __restrict__ ln_g,
        const float* __restrict__ ln_b, const float* __restrict__ W1,
        const float* __restrict__ b1, const float* __restrict__ W2,
        const float* __restrict__ b2, float* __restrict__ out) {
    __shared__ float sln[DD];
    __shared__ float sred[256];
    __shared__ float sh[256];
    int tid = threadIdx.x;
    int b = blockIdx.x;
    const float* p = g_pooled + (size_t)b * DD;
    float s = 0.f, s2 = 0.f;
    for (int d = tid; d < DD; d += 256) {
        float v = p[d];
        sln[d] = v;
        s += v; s2 += v*v;
    }
    sred[tid] = s; __syncthreads();
    for (int st = 128; st > 0; st >>= 1) { if (tid < st) sred[tid] += sred[tid+st]; __syncthreads(); }
    float mu = sred[0] / (float)DD; __syncthreads();
    sred[tid] = s2; __syncthreads();
    for (int st = 128; st > 0; st >>= 1) { if (tid < st) sred[tid] += sred[tid+st]; __syncthreads(); }
    float var = sred[0] / (float)DD - mu*mu; __syncthreads();
    float rstd = rsqrtf(var + 1e-5f);
    for (int d = tid; d < DD; d += 256)
        sln[d] = (sln[d] - mu) * rstd * ln_g[d] + ln_b[d];
    __syncthreads();
    const float* w1r = W1 + (size_t)tid * DD;
    float acc = 0.f;
    for (int d = 0; d < DD; d += 8) {
        #pragma unroll
        for (int u = 0; u < 8; u++) acc += sln[d+u] * w1r[d+u];
    }
    sh[tid] = fmaxf(acc + b1[tid], 0.f);
    __syncthreads();
    sred[tid] = sh[tid] * W2[tid]; __syncthreads();
    for (int st = 128; st > 0; st >>= 1) { if (tid < st) sred[tid] += sred[tid+st]; __syncthreads(); }
    float l0 = sred[0]; __syncthreads();
    sred[tid] = sh[tid] * W2[256 + tid]; __syncthreads();
    for (int st = 128; st > 0; st >>= 1) { if (tid < st) sred[tid] += sred[tid+st]; __syncthreads(); }
    float l1 = sred[0];
    if (tid == 0) {
        l0 += b2[0]; l1 += b2[1];
        float m = fmaxf(l0, l1);
        float lse = m + logf(expf(l0 - m) + expf(l1 - m));
        out[b*2 + 0] = l0 - lse;
        out[b*2 + 1] = l1 - lse;
    }
}

// ---------------- deterministic loss reduction ----------------
__global__ __launch_bounds__(256) void k_loss(float* __restrict__ out) {
    __shared__ float sred[256];
    int tid = threadIdx.x;
    float s = 0.f;
    for (int i = tid; i < NN; i += 256) s += g_losspart[i];
    sred[tid] = s; __syncthreads();
    for (int st = 128; st > 0; st >>= 1) { if (tid < st) sred[tid] += sred[tid+st]; __syncthreads(); }
    if (tid == 0) out[32] = sred[0] / (float)((size_t)NN * CC);
}

// ---------------- launch ----------------
extern "C" void kernel_launch(void* const* d_in, const int* in_sizes, int n_in,
                              void* d_out, int out_size) {
    const float* x     = (const float*)d_in[0];
    const float* W_enc = (const float*)d_in[1];
    const float* b_enc = (const float*)d_in[2];
    const float* b_dec = (const float*)d_in[4];
    const float* ln_g  = (const float*)d_in[5];
    const float* ln_b  = (const float*)d_in[6];
    const float* W1    = (const float*)d_in[7];
    const float* b1    = (const float*)d_in[8];
    const float* W2    = (const float*)d_in[9];
    const float* b2    = (const float*)d_in[10];
    float* out = (float*)d_out;

    cudaFuncSetAttribute(k_gemm_enc_tc,
                         cudaFuncAttributeMaxDynamicSharedMemorySize, 2*STG_F*4);
    cudaFuncSetAttribute(k_wtopk,
                         cudaFuncAttributeMaxDynamicSharedMemorySize, WT_SMEM);

    k_off<<<DD/8, 256>>>(b_enc, b_dec, W_enc);
    k_split_x<<<(NN*CC/4 + 255)/256, 256>>>(x);
    k_split_w<<<(DD*CC/4 + 255)/256, 256>>>(W_enc);
    dim3 gg(NN/128, DD/128);
    k_gemm_enc_tc<<<gg, 256, 2*STG_F*4>>>();
    k_pfix<<<(int)(((size_t)NN*DD)/2048), 256>>>(x, W_enc);
    k_wtopk<<<BB*NW, 512, WT_SMEM>>>(x, W_enc);
    k_ctopk<<<NN, 512>>>(x, W_enc);
    k_zero_pooled<<<(BB*DD + 255)/256, 256>>>();
    k_recon<<<NN, 256>>>(x, b_dec);
    k_head<<<BB, 256>>>(ln_g, ln_b, W1, b1, W2, b2, out);
    k_loss<<<1, 256>>>(out);
}

// round 17
// speedup vs baseline: 1.1227x; 1.1227x over previous
#include <cuda_runtime.h>
#include <cuda_bf16.h>

#define BB 16
#define TT 512
#define CC 1024
#define DD 4096
#define KK 128
#define WW 8
#define NW 127
#define NN (BB*TT)

#define PFIX_DELTA 5e-3f
#define MARGIN_W 5e-2f
#define MARGIN_V 3e-2f
#define BCAP 256
#define ECAP 64

// ---------------- scratch (device globals; no allocation allowed) ----------------
__device__ float g_post[(size_t)NN*DD];            // PRE-activations (no relu); near-zero entries exact
__device__ float g_off[DD];
__device__ unsigned char g_maskw[(size_t)BB*NW*DD];
__device__ unsigned short g_idx[(size_t)NN*KK];
__device__ float g_val[(size_t)NN*KK];
__device__ float g_pooled[BB*DD];
__device__ float g_losspart[NN];
__device__ float g_Ah[(size_t)NN*CC];              // tf32(x)
__device__ float g_Bh[(size_t)DD*CC];              // tf32(W_enc)
__device__ unsigned short g_Wbf[(size_t)DD*CC];    // bf16(W_enc) for recon

__device__ __forceinline__ float to_tf32(float x) {
    float y;
    asm("cvt.rna.tf32.f32 %0, %1;" : "=f"(y) : "f"(x));
    return y;
}
__device__ __forceinline__ void cp16(unsigned dst, const float* src) {
    asm volatile("cp.async.cg.shared.global [%0], [%1], 16;" :: "r"(dst), "l"(src) : "memory");
}

// warp-collective exact fp32 dot (global x, global W): lane-strided chains + shfl tree.
__device__ __forceinline__ float exact_pre_warp(const float* __restrict__ xr,
                                                const float* __restrict__ wr, int lane) {
    float acc = 0.f;
    #pragma unroll 8
    for (int k = lane; k < CC; k += 32) acc = fmaf(xr[k], wr[k], acc);
    #pragma unroll
    for (int o = 16; o; o >>= 1) acc += __shfl_xor_sync(0xffffffffu, acc, o);
    return acc;
}

// ---------------- pre-convert: tf32(x) ----------------
__global__ __launch_bounds__(256) void k_split_x(const float* __restrict__ src) {
    int i = blockIdx.x * blockDim.x + threadIdx.x;
    float4 v = ((const float4*)src)[i];
    float4 h;
    h.x = to_tf32(v.x); h.y = to_tf32(v.y); h.z = to_tf32(v.z); h.w = to_tf32(v.w);
    ((float4*)g_Ah)[i] = h;
}
// ---------------- W: one read -> tf32 copy + bf16 copy ----------------
__global__ __launch_bounds__(256) void k_split_w(const float* __restrict__ src) {
    int i = blockIdx.x * blockDim.x + threadIdx.x;
    float4 v = ((const float4*)src)[i];
    float4 h;
    h.x = to_tf32(v.x); h.y = to_tf32(v.y); h.z = to_tf32(v.z); h.w = to_tf32(v.w);
    ((float4*)g_Bh)[i] = h;
    unsigned b0 = __bfloat16_as_ushort(__float2bfloat16(v.x));
    unsigned b1 = __bfloat16_as_ushort(__float2bfloat16(v.y));
    unsigned b2 = __bfloat16_as_ushort(__float2bfloat16(v.z));
    unsigned b3 = __bfloat16_as_ushort(__float2bfloat16(v.w));
    uint2 o;
    o.x = b0 | (b1 << 16);
    o.y = b2 | (b3 << 16);
    ((uint2*)g_Wbf)[i] = o;
}

// ---------------- offset precompute ----------------
__global__ void k_off(const float* __restrict__ b_enc, const float* __restrict__ b_dec,
                      const float* __restrict__ W_enc) {
    int warp = (blockIdx.x * blockDim.x + threadIdx.x) >> 5;
    int lane = threadIdx.x & 31;
    if (warp >= DD) return;
    const float* wr = W_enc + (size_t)warp * CC;
    float s = 0.f;
    for (int c = lane; c < CC; c += 32) s += b_dec[c] * wr[c];
    #pragma unroll
    for (int o = 16; o; o >>= 1) s += __shfl_down_sync(0xffffffffu, s, o);
    if (lane == 0) g_off[warp] = b_enc[warp] - s;
}

__global__ void k_zero_pooled() {
    int i = blockIdx.x * blockDim.x + threadIdx.x;
    if (i < BB*DD) g_pooled[i] = 0.f;
}

// ---------------- encoder GEMM: SINGLE-term tf32, stores PRE (no relu); 2 blocks/SM --------
#define T_STR 20
#define TILE_F (128*T_STR)
#define STG_F (2*TILE_F)
__global__ __launch_bounds__(256) void k_gemm_enc_tc() {
    extern __shared__ float sm[];
    int tid = threadIdx.x;
    int wid = tid >> 5, lane = tid & 31;
    int g = lane >> 2, tg = lane & 3;
    int wm = wid >> 2, wn = wid & 3;
    const size_t arow = (size_t)blockIdx.x * 128;
    const size_t brow = (size_t)blockIdx.y * 128;
    unsigned smb = (unsigned)__cvta_generic_to_shared(sm);

    float c[4][4][4];
    #pragma unroll
    for (int mi = 0; mi < 4; mi++)
        #pragma unroll
        for (int ni = 0; ni < 4; ni++)
            #pragma unroll
            for (int r = 0; r < 4; r++) c[mi][ni][r] = 0.f;

    auto FILL = [&](int st, int k0) {
        #pragma unroll
        for (int p = 0; p < 2; p++) {
            int ch = tid + p * 256;
            int row = ch >> 2, c4 = (ch & 3) << 2;
            unsigned d = smb + (unsigned)((st*STG_F + row*T_STR + c4) * 4);
            cp16(d,            g_Ah + (arow + row) * CC + k0 + c4);
            cp16(d + TILE_F*4, g_Bh + (brow + row) * CC + k0 + c4);
        }
    };

    FILL(0, 0);
    asm volatile("cp.async.commit_group;" ::: "memory");

    for (int j = 0; j < 64; j++) {
        int s = j & 1;
        if (j < 63) {
            FILL(s ^ 1, (j + 1) * 16);
            asm volatile("cp.async.commit_group;" ::: "memory");
            asm volatile("cp.async.wait_group 1;" ::: "memory");
        } else {
            asm volatile("cp.async.wait_group 0;" ::: "memory");
        }
        __syncthreads();
        const float* Ah = sm + s*STG_F;
        const float* Bh = Ah + TILE_F;
        #pragma unroll
        for (int kk = 0; kk < 2; kk++) {
            int kb = kk * 8;
            unsigned ah[4][4], bh[4][2];
            #pragma unroll
            for (int mi = 0; mi < 4; mi++) {
                int r = wm*64 + mi*16 + g;
                const float* p0 = Ah + r*T_STR + kb + tg;
                ah[mi][0]=__float_as_uint(p0[0]);      ah[mi][1]=__float_as_uint(p0[8*T_STR]);
                ah[mi][2]=__float_as_uint(p0[4]);      ah[mi][3]=__float_as_uint(p0[8*T_STR+4]);
            }
            #pragma unroll
            for (int ni = 0; ni < 4; ni++) {
                int n = wn*32 + ni*8 + g;
                const float* q0 = Bh + n*T_STR + kb + tg;
                bh[ni][0]=__float_as_uint(q0[0]);      bh[ni][1]=__float_as_uint(q0[4]);
            }
            #pragma unroll
            for (int mi = 0; mi < 4; mi++)
                #pragma unroll
                for (int ni = 0; ni < 4; ni++)
                    asm volatile(
                        "mma.sync.aligned.m16n8k8.row.col.f32.tf32.tf32.f32 "
                        "{%0,%1,%2,%3}, {%4,%5,%6,%7}, {%8,%9}, {%0,%1,%2,%3};"
                        : "+f"(c[mi][ni][0]), "+f"(c[mi][ni][1]),
                          "+f"(c[mi][ni][2]), "+f"(c[mi][ni][3])
                        : "r"(ah[mi][0]), "r"(ah[mi][1]), "r"(ah[mi][2]), "r"(ah[mi][3]),
                          "r"(bh[ni][0]), "r"(bh[ni][1]));
        }
        __syncthreads();
    }

    int n0 = (int)arow + wm*64;
    int d0 = (int)brow + wn*32;
    #pragma unroll
    for (int ni = 0; ni < 4; ni++) {
        int col = d0 + ni*8 + 2*tg;
        float o0 = g_off[col], o1 = g_off[col+1];
        #pragma unroll
        for (int mi = 0; mi < 4; mi++) {
            int r0 = n0 + mi*16 + g;
            float2 v0, v1;
            v0.x = c[mi][ni][0] + o0;  v0.y = c[mi][ni][1] + o1;
            v1.x = c[mi][ni][2] + o0;  v1.y = c[mi][ni][3] + o1;
            *(float2*)(g_post + (size_t)r0*DD + col)     = v0;
            *(float2*)(g_post + (size_t)(r0+8)*DD + col) = v1;
        }
    }
}

// ---------------- post-fix: exact recompute of all |pre| <= PFIX_DELTA entries ----------------
__global__ __launch_bounds__(256) void k_pfix(const float* __restrict__ X,
                                              const float* __restrict__ W) {
    int wid = threadIdx.x >> 5, lane = threadIdx.x & 31;
    size_t base = ((size_t)blockIdx.x * 8 + wid) * 256;
    #pragma unroll
    for (int i = 0; i < 8; i++) {
        float v = g_post[base + i*32 + lane];
        unsigned fl = __ballot_sync(0xffffffffu, fabsf(v) <= PFIX_DELTA);
        while (fl) {
            int src = __ffs(fl) - 1; fl &= fl - 1;
            size_t e2 = base + i*32 + src;
            int n = (int)(e2 >> 12), d = (int)(e2 & 4095);
            float p = exact_pre_warp(X + (size_t)n*CC, W + (size_t)d*CC, lane);
            if (lane == src) g_post[e2] = p;
        }
    }
}

// ---------------- exact top-128 of 4096 distinct 44-bit keys: radix + early-exit rank -------
__device__ __forceinline__ unsigned long long radix_select_128(
        const unsigned long long* skey, int tid) {
    __shared__ int hist[256];
    __shared__ unsigned long long sh_prefix;
    __shared__ unsigned long long sh_thr;
    __shared__ unsigned long long elist[ECAP];
    __shared__ int sh_krem, sh_cnt, sh_ecnt;
    if (tid == 0) { sh_prefix = 0ULL; sh_krem = KK; sh_cnt = 1 << 30; }
    __syncthreads();
    int done_shift = -1;
    for (int pass = 0; pass < 6; pass++) {
        int shift = 40 - 8 * pass;
        if (tid < 256) hist[tid] = 0;
        __syncthreads();
        unsigned long long pfx = sh_prefix;
        int krem = sh_krem;
        #pragma unroll
        for (int i = 0; i < 8; i++) {
            unsigned long long key = skey[tid + i * 512];
            bool ok = (pass == 0) || ((key >> (shift + 8)) == (pfx >> (shift + 8)));
            unsigned am = __ballot_sync(0xffffffffu, ok);
            if (ok) {
                int bucket = (int)((key >> shift) & 255ULL);
                unsigned m = __match_any_sync(am, bucket);
                if ((tid & 31) == (__ffs(m) - 1))
                    atomicAdd(&hist[bucket], __popc(m));
            }
        }
        __syncthreads();
        if (tid < 32) {
            int base = tid * 8, suf[8], s = 0;
            #pragma unroll
            for (int j = 7; j >= 0; j--) { s += hist[base + j]; suf[j] = s; }
            int t = s;
            #pragma unroll
            for (int off = 1; off < 32; off <<= 1) {
                int u = __shfl_down_sync(0xffffffffu, t, off);
                if (tid + off < 32) t += u;
            }
            int above = t - s;
            __syncwarp();
            #pragma unroll
            for (int j = 0; j < 8; j++) {
                int Sj = suf[j] + above;
                int Sn = (j < 7 ? suf[j+1] : 0) + above;
                if (Sj >= krem && Sn < krem) {
                    sh_prefix = pfx | ((unsigned long long)(base + j) << shift);
                    sh_krem = krem - Sn;
                    sh_cnt = hist[base + j];
                }
            }
        }
        __syncthreads();
        if (sh_cnt <= ECAP) { done_shift = shift; break; }
    }
    if (done_shift < 0) return sh_prefix;   // all 6 passes done: prefix IS the key
    if (tid == 0) sh_ecnt = 0;
    __syncthreads();
    unsigned long long pfx = sh_prefix;
    #pragma unroll
    for (int i = 0; i < 8; i++) {
        unsigned long long key = skey[tid + i * 512];
        if ((key >> done_shift) == (pfx >> done_shift)) {
            int s = atomicAdd(&sh_ecnt, 1);
            if (s < ECAP) elist[s] = key;
        }
    }
    __syncthreads();
    int cnt = sh_ecnt < ECAP ? sh_ecnt : ECAP;
    int krem = sh_krem;
    if (tid < cnt) {
        int rank = 0;
        for (int j = 0; j < cnt; j++) rank += (elist[j] > elist[tid]);
        if (rank == krem - 1) sh_thr = elist[tid];
    }
    __syncthreads();
    return sh_thr;
}

// ---------------- window sums + top-k mask; smem-staged x, warp-per-candidate fixup ----------
#define WT_SMEM (32768 + 32768 + BCAP*8*4 + BCAP*8 + BCAP*4)
__global__ __launch_bounds__(512) void k_wtopk(const float* __restrict__ X,
                                               const float* __restrict__ W) {
    extern __shared__ char smraw[];
    unsigned long long* skey = (unsigned long long*)smraw;
    float* sx = (float*)(smraw + 32768);
    float (*bd_post)[8] = (float(*)[8])(smraw + 65536);
    unsigned long long* bd_key = (unsigned long long*)(smraw + 65536 + BCAP*32);
    int* bd_d = (int*)(smraw + 65536 + BCAP*32 + BCAP*8);
    __shared__ int sh_bcnt, sh_bin;
    int tid = threadIdx.x;
    int wrp = tid >> 5, lane = tid & 31;
    int b = blockIdx.x / NW, w = blockIdx.x % NW;
    int t0 = w * 4;
    const float* base = g_post + ((size_t)(b*TT + t0)) * DD;
    if (tid == 0) { sh_bcnt = 0; sh_bin = 0; }
    for (int i = tid; i < 8 * CC / 4; i += 512) {
        int t = i / (CC/4), c4 = (i % (CC/4)) * 4;
        *(float4*)&sx[t*CC + c4] = *(const float4*)(X + (size_t)(b*TT + t0 + t)*CC + c4);
    }
    #pragma unroll
    for (int i = 0; i < 8; i++) {
        int d = tid + i * 512;
        float s = 0.f;
        #pragma unroll
        for (int t = 0; t < 8; t++) s += fmaxf(base[(size_t)t*DD + d], 0.f);
        unsigned vb = (s > 0.f) ? __float_as_uint(s) : 0u;
        skey[d] = ((unsigned long long)vb << 12) | (unsigned long long)(0xFFFu - (unsigned)d);
    }
    __syncthreads();
    unsigned long long thr = radix_select_128(skey, tid);
    float thr_val = __uint_as_float((unsigned)(thr >> 12));
    #pragma unroll
    for (int i = 0; i < 8; i++) {
        int d = tid + i * 512;
        unsigned long long key = skey[d];
        float s = __uint_as_float((unsigned)(key >> 12));
        if (fabsf(s - thr_val) <= MARGIN_W) {
            int idx = atomicAdd(&sh_bcnt, 1);
            if (idx < BCAP) {
                bd_d[idx] = d;
                if (key >= thr) atomicAdd(&sh_bin, 1);
            }
        }
    }
    __syncthreads();
    int bcnt = sh_bcnt;
    if (bcnt > BCAP) bcnt = 0;
    int n_need = sh_bin;
    for (int ci = wrp; ci < bcnt; ci += 16) {
        const float* wr = W + (size_t)bd_d[ci] * CC;
        #pragma unroll
        for (int t = 0; t < 8; t++) {
            float acc = 0.f;
            #pragma unroll 8
            for (int k = lane; k < CC; k += 32) acc = fmaf(sx[t*CC + k], wr[k], acc);
            #pragma unroll
            for (int o = 16; o; o >>= 1) acc += __shfl_xor_sync(0xffffffffu, acc, o);
            if (lane == 0) bd_post[ci][t] = fmaxf(acc, 0.f);
        }
    }
    __syncthreads();
    if (tid < bcnt) {
        float s = 0.f;
        #pragma unroll
        for (int t = 0; t < 8; t++) s += bd_post[tid][t];
        unsigned vb = (s > 0.f) ? __float_as_uint(s) : 0u;
        bd_key[tid] = ((unsigned long long)vb << 12) | (unsigned long long)(0xFFFu - (unsigned)bd_d[tid]);
    }
    __syncthreads();
    unsigned char* mw = g_maskw + ((size_t)(b*NW + w)) * DD;
    #pragma unroll
    for (int i = 0; i < 8; i++) {
        int d = tid + i * 512;
        unsigned long long key = skey[d];
        float s = __uint_as_float((unsigned)(key >> 12));
        bool bdy = (bcnt > 0) && (fabsf(s - thr_val) <= MARGIN_W);
        mw[d] = (key >= thr && !bdy) ? (unsigned char)1 : (unsigned char)0;
    }
    __syncthreads();
    if (tid < bcnt) {
        int rank = 0;
        for (int j = 0; j < bcnt; j++) rank += (bd_key[j] > bd_key[tid]);
        mw[bd_d[tid]] = (rank < n_need) ? (unsigned char)1 : (unsigned char)0;
    }
}

// ---------------- votes + combined top-k + sparse encode; smem x; raw-pre candidates ---------
__global__ __launch_bounds__(512) void k_ctopk(const float* __restrict__ X,
                                               const float* __restrict__ W) {
    __shared__ unsigned long long skey[DD];
    __shared__ unsigned char scnt[DD];
    __shared__ float sx[CC];
    __shared__ int bd_d[BCAP];
    __shared__ unsigned char bd_c[BCAP];
    __shared__ float bd_v[BCAP];          // RAW pre (can be negative)
    __shared__ unsigned long long bd_key[BCAP];
    __shared__ int sh_bcnt, sh_bin, s_cnt;
    int tid = threadIdx.x;
    int wrp = tid >> 5, lane = tid & 31;
    int n = blockIdx.x;
    int b = n >> 9, t = n & 511;
    int g = t >> 2;
    const float* pr = g_post + (size_t)n * DD;
    const unsigned char* mw0 = (g >= 1)   ? g_maskw + ((size_t)(b*NW + g-1))*DD : (const unsigned char*)0;
    const unsigned char* mw1 = (g <= 126) ? g_maskw + ((size_t)(b*NW + g  ))*DD : (const unsigned char*)0;
    if (tid == 0) { sh_bcnt = 0; sh_bin = 0; s_cnt = 0; }
    for (int i = tid; i < CC/4; i += 512)
        *(float4*)&sx[i*4] = *(const float4*)(X + (size_t)n*CC + i*4);
    #pragma unroll
    for (int i = 0; i < 8; i++) {
        int d = tid + i * 512;
        float v = fmaxf(pr[d], 0.f);
        int c = (mw0 ? (int)mw0[d] : 0) + (mw1 ? (int)mw1[d] : 0);
        scnt[d] = (unsigned char)c;
        float vote = v * (float)c;
        unsigned vb = (vote > 0.f) ? __float_as_uint(vote) : 0u;
        skey[d] = ((unsigned long long)vb << 12) | (unsigned long long)(0xFFFu - (unsigned)d);
    }
    __syncthreads();
    unsigned long long thr = radix_select_128(skey, tid);
    float thr_val = __uint_as_float((unsigned)(thr >> 12));
    #pragma unroll
    for (int i = 0; i < 8; i++) {
        int d = tid + i * 512;
        unsigned long long key = skey[d];
        float v = __uint_as_float((unsigned)(key >> 12));
        if (scnt[d] > 0 && fabsf(v - thr_val) <= MARGIN_V) {
            int idx = atomicAdd(&sh_bcnt, 1);
            if (idx < BCAP) {
                bd_d[idx] = d;
                bd_c[idx] = scnt[d];
                bd_v[idx] = pr[d];
                if (key >= thr) atomicAdd(&sh_bin, 1);
            }
        }
    }
    __syncthreads();
    int bcnt = sh_bcnt;
    if (bcnt > BCAP) bcnt = 0;
    int n_need = sh_bin;
    for (int ci = wrp; ci < bcnt; ci += 16) {
        float raw = bd_v[ci];
        float pe;
        if (fabsf(raw) <= PFIX_DELTA) {
            pe = fmaxf(raw, 0.f);
        } else {
            const float* wr = W + (size_t)bd_d[ci] * CC;
            float acc = 0.f;
            #pragma unroll 8
            for (int k = lane; k < CC; k += 32) acc = fmaf(sx[k], wr[k], acc);
            #pragma unroll
            for (int o = 16; o; o >>= 1) acc += __shfl_xor_sync(0xffffffffu, acc, o);
            pe = fmaxf(acc, 0.f);
        }
        if (lane == 0) {
            float ve = pe * (float)bd_c[ci];
            unsigned vb = (ve > 0.f) ? __float_as_uint(ve) : 0u;
            bd_key[ci] = ((unsigned long long)vb << 12) | (unsigned long long)(0xFFFu - (unsigned)bd_d[ci]);
        }
    }
    __syncthreads();
    #pragma unroll
    for (int i = 0; i < 8; i++) {
        int d = tid + i * 512;
        unsigned long long key = skey[d];
        float v = __uint_as_float((unsigned)(key >> 12));
        bool bdy = (bcnt > 0) && (scnt[d] > 0) && (fabsf(v - thr_val) <= MARGIN_V);
        if (key >= thr && !bdy) {
            int slot = atomicAdd(&s_cnt, 1);
            g_idx[(size_t)n*KK + slot] = (unsigned short)d;
            g_val[(size_t)n*KK + slot] = fmaxf(pr[d], 0.f);
        }
    }
    __syncthreads();
    if (tid < bcnt) {
        int rank = 0;
        for (int j = 0; j < bcnt; j++) rank += (bd_key[j] > bd_key[tid]);
        if (rank < n_need) {
            int slot = atomicAdd(&s_cnt, 1);
            g_idx[(size_t)n*KK + slot] = (unsigned short)bd_d[tid];
            g_val[(size_t)n*KK + slot] = fmaxf(pr[bd_d[tid]], 0.f);
        }
    }
}

// ---------------- sparse recon (bf16 W) + per-row squared error + pooled accumulation --------
__global__ __launch_bounds__(256) void k_recon(const float* __restrict__ X,
                                               const float* __restrict__ b_dec) {
    __shared__ unsigned short sidx[KK];
    __shared__ float sval[KK];
    __shared__ float sred[256];
    int tid = threadIdx.x;
    int n = blockIdx.x;
    if (tid < KK) {
        sidx[tid] = g_idx[(size_t)n*KK + tid];
        sval[tid] = g_val[(size_t)n*KK + tid];
    }
    __syncthreads();
    int c = tid * 4;
    float4 acc = make_float4(0.f, 0.f, 0.f, 0.f);
    #pragma unroll 4
    for (int j = 0; j < KK; j++) {
        float v = sval[j];
        uint2 p = *(const uint2*)(g_Wbf + (size_t)sidx[j]*CC + c);
        float w0 = __uint_as_float(p.x << 16);
        float w1 = __uint_as_float(p.x & 0xFFFF0000u);
        float w2 = __uint_as_float(p.y << 16);
        float w3 = __uint_as_float(p.y & 0xFFFF0000u);
        acc.x += v*w0; acc.y += v*w1; acc.z += v*w2; acc.w += v*w3;
    }
    float4 bd = *(const float4*)(b_dec + c);
    float4 xv = *(const float4*)(X + (size_t)n*CC + c);
    float dx = acc.x + bd.x - xv.x;
    float dy = acc.y + bd.y - xv.y;
    float dz = acc.z + bd.z - xv.z;
    float dw = acc.w + bd.w - xv.w;
    sred[tid] = dx*dx + dy*dy + dz*dz + dw*dw;
    __syncthreads();
    for (int s = 128; s > 0; s >>= 1) {
        if (tid < s) sred[tid] += sred[tid + s];
        __syncthreads();
    }
    if (tid == 0) g_losspart[n] = sred[0];
    if (tid < KK) {
        int b = n >> 9;
        atomicAdd(&g_pooled[b*DD + sidx[tid]], sval[tid] * (1.f/512.f));
    }
}

// ---------------- LayerNorm + MLP head + log_softmax ----------------
__global__ __launch_bounds__(256) void k_head(const float* __restrict__ ln_g,
        const float* __restrict__ ln_b, const float* __restrict__ W1,
        const float* __restrict__ b1, const float* __restrict__ W2,
        const float* __restrict__ b2, float* __restrict__ out) {
    __shared__ float sln[DD];
    __shared__ float sred[256];
    __shared__ float sh[256];
    int tid = threadIdx.x;
    int b = blockIdx.x;
    const float* p = g_pooled + (size_t)b * DD;
    float s = 0.f, s2 = 0.f;
    for (int d = tid; d < DD; d += 256) {
        float v = p[d];
        sln[d] = v;
        s += v; s2 += v*v;
    }
    sred[tid] = s; __syncthreads();
    for (int st = 128; st > 0; st >>= 1) { if (tid < st) sred[tid] += sred[tid+st]; __syncthreads(); }
    float mu = sred[0] / (float)DD; __syncthreads();
    sred[tid] = s2; __syncthreads();
    for (int st = 128; st > 0; st >>= 1) { if (tid < st) sred[tid] += sred[tid+st]; __syncthreads(); }
    float var = sred[0] / (float)DD - mu*mu; __syncthreads();
    float rstd = rsqrtf(var + 1e-5f);
    for (int d = tid; d < DD; d += 256)
        sln[d] = (sln[d] - mu) * rstd * ln_g[d] + ln_b[d];
    __syncthreads();
    const float* w1r = W1 + (size_t)tid * DD;
    float acc = 0.f;
    for (int d = 0; d < DD; d += 8) {
        #pragma unroll
        for (int u = 0; u < 8; u++) acc += sln[d+u] * w1r[d+u];
    }
    sh[tid] = fmaxf(acc + b1[tid], 0.f);
    __syncthreads();
    sred[tid] = sh[tid] * W2[tid]; __syncthreads();
    for (int st = 128; st > 0; st >>= 1) { if (tid < st) sred[tid] += sred[tid+st]; __syncthreads(); }
    float l0 = sred[0]; __syncthreads();
    sred[tid] = sh[tid] * W2[256 + tid]; __syncthreads();
    for (int st = 128; st > 0; st >>= 1) { if (tid < st) sred[tid] += sred[tid+st]; __syncthreads(); }
    float l1 = sred[0];
    if (tid == 0) {
        l0 += b2[0]; l1 += b2[1];
        float m = fmaxf(l0, l1);
        float lse = m + logf(expf(l0 - m) + expf(l1 - m));
        out[b*2 + 0] = l0 - lse;
        out[b*2 + 1] = l1 - lse;
    }
}

// ---------------- deterministic loss reduction ----------------
__global__ __launch_bounds__(256) void k_loss(float* __restrict__ out) {
    __shared__ float sred[256];
    int tid = threadIdx.x;
    float s = 0.f;
    for (int i = tid; i < NN; i += 256) s += g_losspart[i];
    sred[tid] = s; __syncthreads();
    for (int st = 128; st > 0; st >>= 1) { if (tid < st) sred[tid] += sred[tid+st]; __syncthreads(); }
    if (tid == 0) out[32] = sred[0] / (float)((size_t)NN * CC);
}

// ---------------- launch ----------------
extern "C" void kernel_launch(void* const* d_in, const int* in_sizes, int n_in,
                              void* d_out, int out_size) {
    const float* x     = (const float*)d_in[0];
    const float* W_enc = (const float*)d_in[1];
    const float* b_enc = (const float*)d_in[2];
    const float* b_dec = (const float*)d_in[4];
    const float* ln_g  = (const float*)d_in[5];
    const float* ln_b  = (const float*)d_in[6];
    const float* W1    = (const float*)d_in[7];
    const float* b1    = (const float*)d_in[8];
    const float* W2    = (const float*)d_in[9];
    const float* b2    = (const float*)d_in[10];
    float* out = (float*)d_out;

    cudaFuncSetAttribute(k_gemm_enc_tc,
                         cudaFuncAttributeMaxDynamicSharedMemorySize, 2*STG_F*4);
    cudaFuncSetAttribute(k_wtopk,
                         cudaFuncAttributeMaxDynamicSharedMemorySize, WT_SMEM);

    k_off<<<DD/8, 256>>>(b_enc, b_dec, W_enc);
    k_split_x<<<(NN*CC/4 + 255)/256, 256>>>(x);
    k_split_w<<<(DD*CC/4 + 255)/256, 256>>>(W_enc);
    dim3 gg(NN/128, DD/128);
    k_gemm_enc_tc<<<gg, 256, 2*STG_F*4>>>();
    k_pfix<<<(int)(((size_t)NN*DD)/2048), 256>>>(x, W_enc);
    k_wtopk<<<BB*NW, 512, WT_SMEM>>>(x, W_enc);
    k_ctopk<<<NN, 512>>>(x, W_enc);
    k_zero_pooled<<<(BB*DD + 255)/256, 256>>>();
    k_recon<<<NN, 256>>>(x, b_dec);
    k_head<<<BB, 256>>>(ln_g, ln_b, W1, b1, W2, b2, out);
    k_loss<<<1, 256>>>(out);
}